// round 3
// baseline (speedup 1.0000x reference)
#include <cuda_runtime.h>
#include <cuda_bf16.h>

// LinearPositionInterpolation:
//   index: (n,) int32 sorted keypoints (n=129, spacing 32 -> m=4096)
//   value: (batch, n, dim) float32   (batch=32, dim=256)
//   out:   (batch, m, dim) float32, rows p=1..m (excludes start point)
//
// R3: single-wave persistent-ish grid. 1024 blocks x 256 threads, each block
// handles exactly TILES_PER_BLOCK=4 consecutive (batch,segment) tiles.
// All 1024 blocks are co-resident (7 blocks/SM on 148 SMs) -> one scheduling
// wave, no tail quantization, block startup amortized 4x. Default (write-back)
// stores so L2 absorbs the stream and drains overlapped with the next replay.

static constexpr int DIM   = 256;          // per metadata
static constexpr int DIM4  = DIM / 4;      // 64 float4 lanes per row
static constexpr int RLANE = 4;            // rows in flight per block
static constexpr int TPB   = DIM4 * RLANE; // 256 threads
static constexpr int TILES_PER_BLOCK = 4;

__global__ __launch_bounds__(TPB, 7)
void lpi_kernel(const int* __restrict__ index,
                const float4* __restrict__ value,
                float4* __restrict__ out,
                int n, int m, int ntiles)
{
    const int nseg = n - 1;
    const int d    = threadIdx.x & (DIM4 - 1);   // dim lane 0..63
    const int rl   = threadIdx.x >> 6;           // row lane 0..3
    const int base = index[0];

    const int tile0 = blockIdx.x * TILES_PER_BLOCK;

    #pragma unroll 1
    for (int tt = 0; tt < TILES_PER_BLOCK; tt++) {
        const int tile = tile0 + tt;
        if (tile >= ntiles) break;

        const int seg = tile % nseg;
        const int b   = tile / nseg;

        const int x0  = index[seg]     - base;   // L2-hot
        const int x1  = index[seg + 1] - base;
        const int len = x1 - x0;
        const float inv = 1.0f / (float)len;

        const float4* v = value + ((long long)b * n + seg) * DIM4 + d;
        const float4 y0 = __ldg(v);
        const float4 y1 = __ldg(v + DIM4);
        const float4 dy = make_float4(y1.x - y0.x, y1.y - y0.y,
                                      y1.z - y0.z, y1.w - y0.w);

        // output row for p = x0 + pc is (x0 + pc - 1) (0-based, p starts at 1)
        float4* o = out + ((long long)(b * m + x0) + rl) * DIM4 + d;
        const long long ostep = (long long)RLANE * DIM4;

        #pragma unroll 4
        for (int pc = 1 + rl; pc <= len; pc += RLANE) {
            const float w = (float)pc * inv;
            float4 r;
            r.x = fmaf(dy.x, w, y0.x);
            r.y = fmaf(dy.y, w, y0.y);
            r.z = fmaf(dy.z, w, y0.z);
            r.w = fmaf(dy.w, w, y0.w);
            *o = r;
            o += ostep;
        }
    }
}

extern "C" void kernel_launch(void* const* d_in, const int* in_sizes, int n_in,
                              void* d_out, int out_size)
{
    const int*    index = (const int*)d_in[0];
    const float4* value = (const float4*)d_in[1];
    float4*       out   = (float4*)d_out;

    const int n     = in_sizes[0];                 // 129
    const int batch = in_sizes[1] / (n * DIM);     // 32
    const int m     = out_size / (batch * DIM);    // 4096

    const int ntiles = batch * (n - 1);            // 4096
    const int grid   = (ntiles + TILES_PER_BLOCK - 1) / TILES_PER_BLOCK; // 1024

    lpi_kernel<<<grid, TPB>>>(index, value, out, n, m, ntiles);
}

// round 4
// speedup vs baseline: 1.0754x; 1.0754x over previous
#include <cuda_runtime.h>
#include <cuda_bf16.h>

// LinearPositionInterpolation:
//   index: (n,) int32 sorted keypoints (n=129, spacing 32 -> m=4096)
//   value: (batch, n, dim) float32   (batch=32, dim=256)
//   out:   (batch, m, dim) float32, rows p=1..m (excludes start point)
//
// R4 = R1 geometry (4096 blocks x 64 threads; each block owns one (b,seg)
// tile = one contiguous 32KB output region) + R2's evict-first streaming
// stores + 32-bit addressing + unroll 8 (eight independent STG.128 in
// flight per thread per loop body).

static constexpr int DIM  = 256;      // per metadata
static constexpr int DIM4 = DIM / 4;  // 64 float4 lanes per row

__global__ __launch_bounds__(DIM4, 32)
void lpi_kernel(const int* __restrict__ index,
                const float4* __restrict__ value,
                float4* __restrict__ out,
                int n, int m)
{
    const int nseg = n - 1;
    const int seg  = blockIdx.x % nseg;
    const int b    = blockIdx.x / nseg;
    const int d    = threadIdx.x;            // 0..63

    const int base = index[0];
    const int x0   = index[seg]     - base;  // L2-hot after first touch
    const int x1   = index[seg + 1] - base;
    const int len  = x1 - x0;                // rows in this segment
    const float inv = 1.0f / (float)len;

    // 32-bit element offsets: max is 32*129*64 (~264K) for value,
    // 32*4096*64 (~8.4M) for out — both well within int range.
    const float4* v = value + (b * n + seg) * DIM4 + d;
    const float4 y0 = __ldg(v);
    const float4 y1 = __ldg(v + DIM4);
    const float4 dy = make_float4(y1.x - y0.x, y1.y - y0.y,
                                  y1.z - y0.z, y1.w - y0.w);

    // output row for p = x0 + pc is (x0 + pc - 1) (0-based, p starts at 1)
    float4* o = out + (b * m + x0) * DIM4 + d;

    #pragma unroll 8
    for (int pc = 1; pc <= len; pc++) {
        const float w = (float)pc * inv;
        float4 r;
        r.x = fmaf(dy.x, w, y0.x);
        r.y = fmaf(dy.y, w, y0.y);
        r.z = fmaf(dy.z, w, y0.z);
        r.w = fmaf(dy.w, w, y0.w);
        __stcs(o + (pc - 1) * DIM4, r);      // evict-first streaming store
    }
}

extern "C" void kernel_launch(void* const* d_in, const int* in_sizes, int n_in,
                              void* d_out, int out_size)
{
    const int*    index = (const int*)d_in[0];
    const float4* value = (const float4*)d_in[1];
    float4*       out   = (float4*)d_out;

    const int n     = in_sizes[0];                 // 129
    const int batch = in_sizes[1] / (n * DIM);     // 32
    const int m     = out_size / (batch * DIM);    // 4096

    const int nseg = n - 1;
    dim3 grid(batch * nseg);                       // 4096 blocks
    dim3 block(DIM4);                              // 64 threads
    lpi_kernel<<<grid, block>>>(index, value, out, n, m);
}

// round 5
// speedup vs baseline: 1.1454x; 1.0651x over previous
#include <cuda_runtime.h>
#include <cuda_bf16.h>

// LinearPositionInterpolation:
//   index: (n,) int32 sorted keypoints (n=129, spacing 32 -> m=4096)
//   value: (batch, n, dim) float32   (batch=32, dim=256)
//   out:   (batch, m, dim) float32, rows p=1..m (excludes start point)
//
// R5 = R2 shape (one block per (b,seg) tile, 256 threads, interleaved row
// lanes, evict-first streaming stores) + Blackwell 256-bit vector memory ops:
// each thread owns 8 floats (32 B), a warp writes a full 1 KB row per STG.256.
// Halves store/load instruction count vs float4 at identical traffic.

static constexpr int DIM  = 256;       // per metadata
static constexpr int DIM8 = DIM / 8;   // 32 v8-lanes per row (one warp/row)
static constexpr int RL   = 8;         // row lanes per block
static constexpr int TPB  = DIM8 * RL; // 256 threads

__device__ __forceinline__ void ldg_nc_v8(float (&r)[8], const float* p) {
    asm volatile("ld.global.nc.v8.f32 {%0,%1,%2,%3,%4,%5,%6,%7}, [%8];"
                 : "=f"(r[0]), "=f"(r[1]), "=f"(r[2]), "=f"(r[3]),
                   "=f"(r[4]), "=f"(r[5]), "=f"(r[6]), "=f"(r[7])
                 : "l"(p));
}

__device__ __forceinline__ void stg_cs_v8(float* p, const float (&r)[8]) {
    asm volatile("st.global.cs.v8.f32 [%0], {%1,%2,%3,%4,%5,%6,%7,%8};"
                 :: "l"(p),
                    "f"(r[0]), "f"(r[1]), "f"(r[2]), "f"(r[3]),
                    "f"(r[4]), "f"(r[5]), "f"(r[6]), "f"(r[7])
                 : "memory");
}

__global__ __launch_bounds__(TPB, 8)
void lpi_kernel(const int* __restrict__ index,
                const float* __restrict__ value,
                float* __restrict__ out,
                int n, int m)
{
    const int nseg = n - 1;
    const int seg  = blockIdx.x % nseg;
    const int b    = blockIdx.x / nseg;
    const int d    = threadIdx.x & (DIM8 - 1);   // v8 dim lane 0..31
    const int rl   = threadIdx.x >> 5;           // row lane 0..7

    const int base = index[0];
    const int x0   = index[seg]     - base;      // L2-hot
    const int x1   = index[seg + 1] - base;
    const int len  = x1 - x0;                    // rows in this segment
    const float inv = 1.0f / (float)len;

    const float* v = value + (b * n + seg) * DIM + d * 8;
    float y0[8], y1[8];
    ldg_nc_v8(y0, v);
    ldg_nc_v8(y1, v + DIM);

    float dy[8];
    #pragma unroll
    for (int i = 0; i < 8; i++) dy[i] = y1[i] - y0[i];

    // output row for p = x0 + pc is (x0 + pc - 1) (0-based, p starts at 1)
    float* o = out + (b * m + x0 + rl) * DIM + d * 8;

    #pragma unroll 4
    for (int pc = 1 + rl; pc <= len; pc += RL) {
        const float w = (float)pc * inv;
        float r[8];
        #pragma unroll
        for (int i = 0; i < 8; i++) r[i] = fmaf(dy[i], w, y0[i]);
        stg_cs_v8(o, r);
        o += RL * DIM;
    }
}

extern "C" void kernel_launch(void* const* d_in, const int* in_sizes, int n_in,
                              void* d_out, int out_size)
{
    const int*   index = (const int*)d_in[0];
    const float* value = (const float*)d_in[1];
    float*       out   = (float*)d_out;

    const int n     = in_sizes[0];                 // 129
    const int batch = in_sizes[1] / (n * DIM);     // 32
    const int m     = out_size / (batch * DIM);    // 4096

    const int nseg = n - 1;
    dim3 grid(batch * nseg);                       // 4096 blocks
    dim3 block(TPB);                               // 256 threads
    lpi_kernel<<<grid, block>>>(index, value, out, n, m);
}

// round 6
// speedup vs baseline: 1.2335x; 1.0769x over previous
#include <cuda_runtime.h>
#include <cuda_bf16.h>

// LinearPositionInterpolation:
//   index: (n,) int32 sorted keypoints (n=129, spacing 32 -> m=4096)
//   value: (batch, n, dim) float32   (batch=32, dim=256)
//   out:   (batch, m, dim) float32, rows p=1..m (excludes start point)
//
// R6: max-occupancy steady-state build. 2 blocks per (b,seg) tile, 128
// threads each (4 row-lanes x 32 float4 dim-lanes), global row stride 8.
// __launch_bounds__(128,16) -> 2048 threads/SM (100% occupancy) to hide
// L2 dirty-eviction stalls during graph-replay steady state. Evict-first
// (.cs) float4 stores (best replay behavior across R1-R5).

static constexpr int DIM    = 256;       // per metadata
static constexpr int DIM4   = DIM / 4;   // 64 float4 lanes per row
static constexpr int HALF   = 2;         // blocks per tile
static constexpr int RL     = 4;         // row lanes per block
static constexpr int GRL    = HALF * RL; // 8 global row lanes per tile
static constexpr int TPB    = 128;       // (DIM4/2)*... = 32 dim lanes? no:

// Layout inside a block: 128 threads = 4 row lanes x 32 float4 lanes?
// DIM4=64 lanes needed per row -> use 2 row lanes x 64 dim lanes instead.
// Rework: TPB=128 = 64 dim lanes x 2 row lanes; 2 blocks/tile -> 4 global
// row lanes, stride 4.

static constexpr int RLANES_BLK  = 2;                 // row lanes per block
static constexpr int RLANES_TILE = HALF * RLANES_BLK; // 4 per tile

__global__ __launch_bounds__(TPB, 16)
void lpi_kernel(const int* __restrict__ index,
                const float4* __restrict__ value,
                float4* __restrict__ out,
                int n, int m)
{
    const int nseg = n - 1;
    const int tile = blockIdx.x >> 1;          // (b,seg) tile
    const int half = blockIdx.x & 1;           // which half of row set
    const int seg  = tile % nseg;
    const int b    = tile / nseg;
    const int d    = threadIdx.x & (DIM4 - 1); // dim lane 0..63
    const int rl   = (threadIdx.x >> 6) + half * RLANES_BLK; // global row lane 0..3

    const int base = index[0];
    const int x0   = index[seg]     - base;    // L2-hot
    const int x1   = index[seg + 1] - base;
    const int len  = x1 - x0;                  // rows in this segment
    const float inv = 1.0f / (float)len;

    const float4* v = value + (b * n + seg) * DIM4 + d;
    const float4 y0 = __ldg(v);
    const float4 y1 = __ldg(v + DIM4);
    const float4 dy = make_float4(y1.x - y0.x, y1.y - y0.y,
                                  y1.z - y0.z, y1.w - y0.w);

    // output row for p = x0 + pc is (x0 + pc - 1) (0-based, p starts at 1)
    float4* o = out + (b * m + x0 + rl) * DIM4 + d;
    const int ostep = RLANES_TILE * DIM4;

    #pragma unroll 8
    for (int pc = 1 + rl; pc <= len; pc += RLANES_TILE) {
        const float w = (float)pc * inv;
        float4 r;
        r.x = fmaf(dy.x, w, y0.x);
        r.y = fmaf(dy.y, w, y0.y);
        r.z = fmaf(dy.z, w, y0.z);
        r.w = fmaf(dy.w, w, y0.w);
        __stcs(o, r);                          // evict-first streaming store
        o += ostep;
    }
}

extern "C" void kernel_launch(void* const* d_in, const int* in_sizes, int n_in,
                              void* d_out, int out_size)
{
    const int*    index = (const int*)d_in[0];
    const float4* value = (const float4*)d_in[1];
    float4*       out   = (float4*)d_out;

    const int n     = in_sizes[0];                 // 129
    const int batch = in_sizes[1] / (n * DIM);     // 32
    const int m     = out_size / (batch * DIM);    // 4096

    const int nseg = n - 1;
    dim3 grid(batch * nseg * HALF);                // 8192 blocks
    dim3 block(TPB);                               // 128 threads
    lpi_kernel<<<grid, block>>>(index, value, out, n, m);
}